// round 10
// baseline (speedup 1.0000x reference)
#include <cuda_runtime.h>
#include <cuda_bf16.h>
#include <math_constants.h>
#include <cstdint>

#define DM   1024
#define HS   64
#define BB   4
#define TT   2048
#define ROWS (BB * TT)        /* 8192 */
#define NS   8                /* key splits (SPLIT = 256) */
#define SPLIT 256
#define TRI2 72               /* sum ceil((qt+1)/2), qt=0..15 */
#define NCOL 192
#define SCV  11.541560327111707f   /* 8 * log2(e) */

typedef unsigned long long u64;

/* ---------------- helpers ------------------------------------------------ */
__device__ __forceinline__ unsigned pk_bf2(float a, float b) {
    unsigned r;
    asm("cvt.rn.bf16x2.f32 %0, %1, %2;" : "=r"(r) : "f"(b), "f"(a));
    return r;
}
__device__ __forceinline__ void mma_bf16(float* d, const unsigned* a, const unsigned* b) {
    asm volatile(
        "mma.sync.aligned.m16n8k16.row.col.f32.bf16.bf16.f32 "
        "{%0,%1,%2,%3}, {%4,%5,%6,%7}, {%8,%9}, {%0,%1,%2,%3};"
        : "+f"(d[0]), "+f"(d[1]), "+f"(d[2]), "+f"(d[3])
        : "r"(a[0]), "r"(a[1]), "r"(a[2]), "r"(a[3]), "r"(b[0]), "r"(b[1]));
}
__device__ __forceinline__ void ldsm_x4(unsigned* r, uint32_t addr) {
    asm volatile("ldmatrix.sync.aligned.m8n8.x4.shared.b16 {%0,%1,%2,%3}, [%4];"
        : "=r"(r[0]), "=r"(r[1]), "=r"(r[2]), "=r"(r[3]) : "r"(addr));
}
__device__ __forceinline__ uint32_t smem_u32(const void* p) {
    uint32_t a;
    asm("{ .reg .u64 t; cvta.to.shared.u64 t, %1; cvt.u32.u64 %0, t; }"
        : "=r"(a) : "l"(p));
    return a;
}
__device__ __forceinline__ void cp16(uint32_t dst, const void* src) {
    asm volatile("cp.async.cg.shared.global [%0], [%1], 16;" :: "r"(dst), "l"(src));
}
#define CP_COMMIT() asm volatile("cp.async.commit_group;" ::: "memory")
#define CP_WAIT0()  asm volatile("cp.async.wait_group 0;" ::: "memory")

__device__ __forceinline__ void split4(float4 v, u64& hi, u64& lo) {
    unsigned h01 = pk_bf2(v.x, v.y), h23 = pk_bf2(v.z, v.w);
    float h0 = __uint_as_float(h01 << 16);
    float h1 = __uint_as_float(h01 & 0xffff0000u);
    float h2 = __uint_as_float(h23 << 16);
    float h3 = __uint_as_float(h23 & 0xffff0000u);
    unsigned l01 = pk_bf2(v.x - h0, v.y - h1), l23 = pk_bf2(v.z - h2, v.w - h3);
    hi = ((u64)h23 << 32) | h01;
    lo = ((u64)l23 << 32) | l01;
}

/* ---------------- device scratch ---------------------------------------- */
__device__ u64 g_Bh[NCOL * DM / 4];
__device__ u64 g_Bl[NCOL * DM / 4];
__device__ uint16_t g_qh[ROWS * HS], g_ql[ROWS * HS];
__device__ uint16_t g_kh[ROWS * HS], g_kl[ROWS * HS];
__device__ uint16_t g_vth[BB * HS * TT], g_vtl[BB * HS * TT];
__device__ float g_po[(size_t)NS * ROWS * HS];
__device__ float g_pm[NS * ROWS];
__device__ float g_pl[NS * ROWS];

/* ---------------- build fused transposed weight B[n][k] ------------------ */
__global__ __launch_bounds__(256)
void build_b_kernel(const float* __restrict__ Wq, const float* __restrict__ Wk,
                    const float* __restrict__ Wv) {
    int i = blockIdx.x * 256 + threadIdx.x;
    int n = i >> 10, k = i & 1023;
    const float* W = (n < 64) ? Wq : ((n < 128) ? Wk : Wv);
    float v = W[(size_t)k * HS + (n & 63)];
    unsigned hp = pk_bf2(v, 0.f);
    float h = __uint_as_float(hp << 16);
    unsigned lp = pk_bf2(v - h, 0.f);
    ((uint16_t*)g_Bh)[i] = (uint16_t)(hp & 0xffffu);
    ((uint16_t*)g_Bl)[i] = (uint16_t)(lp & 0xffffu);
}

/* ---------------- QKV GEMM: double-buffered K16 chunks + cp.async B -----
 * Buffer layout (per buf, 18432 B): Ah[128x48] | Al | Bh[64x48] | Bl.
 * One __syncthreads per chunk; loads for c+1 overlap MMA of c. */
#define QBUF 18432
#define TPITCH 132
__global__ __launch_bounds__(256)
void qkv_mma_kernel(const float* __restrict__ x,
                    const float* __restrict__ bq, const float* __restrict__ bk) {
    __shared__ __align__(128) uint8_t sbuf[2 * QBUF];   /* 36864; epilogue sT = 33792 */
    float* sT = (float*)sbuf;

    const int tid   = threadIdx.x;
    const int which = blockIdx.y;
    const int row0  = blockIdx.x * 128;
    const int w     = tid >> 5;
    const int lane  = tid & 31;
    const int wm    = w & 3;
    const int wn    = w >> 2;
    const int g     = lane >> 2;
    const int tig   = lane & 3;
    const uint32_t sb = smem_u32(sbuf);
    const int l7  = lane & 7;
    const int q01 = (lane >> 3) & 1;
    const int q2  = lane >> 4;

    /* A loader: 2 float4/thread: item i -> row i>>2, seg i&3 */
    int arow[2], aseg[2];
    #pragma unroll
    for (int t = 0; t < 2; t++) { int i = tid + t * 256; arow[t] = i >> 2; aseg[t] = i & 3; }
    /* B loader: 1 cp.async/thread */
    const int barr = (tid >> 7) & 1, brow = (tid >> 1) & 63, bseg = tid & 1;
    const uint8_t* bsrc = (const uint8_t*)(barr ? (const void*)g_Bl : (const void*)g_Bh);

    float acc[2][4][4];
    #pragma unroll
    for (int mt = 0; mt < 2; mt++)
        #pragma unroll
        for (int nt = 0; nt < 4; nt++)
            #pragma unroll
            for (int e = 0; e < 4; e++) acc[mt][nt][e] = 0.f;

    float4 fa[2][2];
    #pragma unroll
    for (int t = 0; t < 2; t++)
        fa[0][t] = *(const float4*)(x + (size_t)(row0 + arow[t]) * DM + aseg[t] * 4);
    cp16(sb + 12288 + barr * 3072 + brow * 48 + bseg * 16,
         bsrc + ((size_t)(which * 64 + brow) * 1024 + bseg * 8) * 2);
    CP_COMMIT();

    #pragma unroll 2
    for (int c = 0; c < 64; c++) {
        const int cur = c & 1;
        const uint32_t bb = sb + cur * QBUF;
        uint8_t* bp = sbuf + cur * QBUF;
        /* store A chunk c (convert fp32 -> bf16 hi/lo) */
        #pragma unroll
        for (int t = 0; t < 2; t++) {
            u64 hi, lo;
            split4(fa[cur][t], hi, lo);
            *(u64*)(bp + arow[t] * 48 + aseg[t] * 8)        = hi;
            *(u64*)(bp + 6144 + arow[t] * 48 + aseg[t] * 8) = lo;
        }
        /* prefetch A chunk c+1 (regs only, no hazard) */
        if (c < 63) {
            #pragma unroll
            for (int t = 0; t < 2; t++)
                fa[1 - cur][t] = *(const float4*)(x + (size_t)(row0 + arow[t]) * DM
                                                    + (c + 1) * 16 + aseg[t] * 4);
        }
        CP_WAIT0();                /* B chunk c landed */
        __syncthreads();           /* buf published; MMA(c-1) on other buf done */
        if (c < 63) {              /* B chunk c+1 into the other buffer */
            cp16(sb + (1 - cur) * QBUF + 12288 + barr * 3072 + brow * 48 + bseg * 16,
                 bsrc + ((size_t)(which * 64 + brow) * 1024 + (c + 1) * 16 + bseg * 8) * 2);
            CP_COMMIT();
        }

        /* MMA chunk c (K=16) */
        unsigned ah[2][4], al[2][4], bhv[2][4], blv[2][4];
        #pragma unroll
        for (int mt = 0; mt < 2; mt++) {
            uint32_t aoff = bb + (uint32_t)((wm * 32 + mt * 16 + q01 * 8 + l7) * 48 + q2 * 16);
            ldsm_x4(ah[mt], aoff);
            ldsm_x4(al[mt], aoff + 6144);
        }
        #pragma unroll
        for (int p = 0; p < 2; p++) {
            uint32_t boff = bb + 12288 + (uint32_t)((wn * 32 + p * 16 + q2 * 8 + l7) * 48 + q01 * 16);
            ldsm_x4(bhv[p], boff);
            ldsm_x4(blv[p], boff + 3072);
        }
        #pragma unroll
        for (int mt = 0; mt < 2; mt++)
            #pragma unroll
            for (int nt = 0; nt < 4; nt++) {
                const unsigned* bh = &bhv[nt >> 1][(nt & 1) * 2];
                const unsigned* bl = &blv[nt >> 1][(nt & 1) * 2];
                mma_bf16(acc[mt][nt], ah[mt], bh);
                mma_bf16(acc[mt][nt], ah[mt], bl);
                mma_bf16(acc[mt][nt], al[mt], bh);
            }
    }

    if (which < 2) {
        uint16_t* dh = (which == 0) ? g_qh : g_kh;
        uint16_t* dl = (which == 0) ? g_ql : g_kl;
        const float* bias = (which == 0) ? bq : bk;
        #pragma unroll
        for (int mt = 0; mt < 2; mt++) {
            #pragma unroll
            for (int nt = 0; nt < 4; nt++) {
                int m = row0 + wm * 32 + mt * 16 + g;
                int n = wn * 32 + nt * 8 + tig * 2;
                float bx = bias[n], by = bias[n + 1];
                float v0x = acc[mt][nt][0] + bx, v0y = acc[mt][nt][1] + by;
                float v1x = acc[mt][nt][2] + bx, v1y = acc[mt][nt][3] + by;
                unsigned h0 = pk_bf2(v0x, v0y);
                unsigned h1 = pk_bf2(v1x, v1y);
                float h0x = __uint_as_float(h0 << 16);
                float h0y = __uint_as_float(h0 & 0xffff0000u);
                float h1x = __uint_as_float(h1 << 16);
                float h1y = __uint_as_float(h1 & 0xffff0000u);
                *(unsigned*)&dh[(size_t)m * HS + n]        = h0;
                *(unsigned*)&dl[(size_t)m * HS + n]        = pk_bf2(v0x - h0x, v0y - h0y);
                *(unsigned*)&dh[(size_t)(m + 8) * HS + n]  = h1;
                *(unsigned*)&dl[(size_t)(m + 8) * HS + n]  = pk_bf2(v1x - h1x, v1y - h1y);
            }
        }
    } else {
        __syncthreads();           /* all MMA reads done before overwriting sbuf */
        #pragma unroll
        for (int mt = 0; mt < 2; mt++) {
            #pragma unroll
            for (int nt = 0; nt < 4; nt++) {
                int ml = wm * 32 + mt * 16 + g;
                int n  = wn * 32 + nt * 8 + tig * 2;
                sT[n * TPITCH + ml]             = acc[mt][nt][0];
                sT[(n + 1) * TPITCH + ml]       = acc[mt][nt][1];
                sT[n * TPITCH + ml + 8]         = acc[mt][nt][2];
                sT[(n + 1) * TPITCH + ml + 8]   = acc[mt][nt][3];
            }
        }
        __syncthreads();
        const int b  = row0 >> 11;
        const int t0 = row0 & (TT - 1);
        #pragma unroll
        for (int t4 = 0; t4 < 8; t4++) {
            int idx = tid + t4 * 256;
            int d = idx >> 5, j = idx & 31;
            float4 v = *(const float4*)&sT[d * TPITCH + 4 * j];
            u64 hi, lo;
            split4(v, hi, lo);
            size_t o = ((size_t)(b * HS + d)) * TT + t0 + 4 * j;
            *(u64*)&g_vth[o] = hi;
            *(u64*)&g_vtl[o] = lo;
        }
    }
}

/* ---------------- causal flash-attention: cp.async double-buffer --------
 * 32-key chunks. Per buf (19456 B): Kh[32x144] | Kl | Vh[64x80] | Vl. */
#define ABUF 19456
__global__ __launch_bounds__(256)
void attn_mma_kernel() {
    int t = blockIdx.x;
    int b = blockIdx.y;
    int qt = 0, cum = 0;
    #pragma unroll
    for (int i = 0; i < 16; i++) {
        int cnt = (i + 2) >> 1;
        if (t < cum + cnt) { qt = i; break; }
        cum += cnt;
    }
    const int kb = t - cum;

    const int tid  = threadIdx.x;
    const int w    = tid >> 5;
    const int lane = tid & 31;
    const int g    = lane >> 2;
    const int tig  = lane & 3;
    const int r0   = qt * 128 + w * 16;
    const int bT   = b * TT;
    const int kend = qt * 128 + 128;
    const int nch  = min(8, (kend - kb * SPLIT + 31) >> 5);

    __shared__ __align__(128) uint8_t sbuf[2 * ABUF];   /* 38912 */
    const uint32_t sb = smem_u32(sbuf);
    const int l7 = lane & 7;
    const int q4 = lane >> 3;

    /* chunk loader: 4 cp.async/thread */
    const int ko_arr = tid >> 8;                 /* 0 for tid<256 trick unused */
    (void)ko_arr;

    /* Q fragments */
    unsigned qh[4][4], ql[4][4];
    {
        const uint16_t* qah = g_qh + (size_t)(bT + r0 + g) * HS;
        const uint16_t* qal = g_ql + (size_t)(bT + r0 + g) * HS;
        #pragma unroll
        for (int kq = 0; kq < 4; kq++) {
            int c = kq * 16 + 2 * tig;
            qh[kq][0] = *(const unsigned*)(qah + c);
            qh[kq][1] = *(const unsigned*)(qah + 8 * HS + c);
            qh[kq][2] = *(const unsigned*)(qah + c + 8);
            qh[kq][3] = *(const unsigned*)(qah + 8 * HS + c + 8);
            ql[kq][0] = *(const unsigned*)(qal + c);
            ql[kq][1] = *(const unsigned*)(qal + 8 * HS + c);
            ql[kq][2] = *(const unsigned*)(qal + c + 8);
            ql[kq][3] = *(const unsigned*)(qal + 8 * HS + c + 8);
        }
    }

    float o[8][4];
    #pragma unroll
    for (int i = 0; i < 8; i++)
        #pragma unroll
        for (int e = 0; e < 4; e++) o[i][e] = 0.f;
    float m_a = -CUDART_INF_F, m_b = -CUDART_INF_F;
    float l_a = 0.f, l_b = 0.f;
    const int ra = r0 + g, rb = r0 + g + 8;

    /* issue chunk loader lambda-ish via macro: 4 ops per thread */
    #define ISSUE_CHUNK(j0v, bufb) do {                                             \
        int _j0 = (j0v); uint32_t _d = sb + (bufb) * ABUF;                          \
        _Pragma("unroll")                                                           \
        for (int _t = 0; _t < 2; _t++) {   /* K: ops 0..511 */                      \
            int _o = tid + _t * 256;                                                \
            int _arr = _o >> 8, _row = (_o >> 3) & 31, _seg = _o & 7;               \
            const uint16_t* _src = (_arr ? g_kl : g_kh)                             \
                + (size_t)(bT + _j0 + _row) * HS + _seg * 8;                        \
            cp16(_d + _arr * 4608 + _row * 144 + _seg * 16, _src);                  \
        }                                                                           \
        _Pragma("unroll")                                                           \
        for (int _t = 0; _t < 2; _t++) {   /* V: ops 0..511 */                      \
            int _o = tid + _t * 256;                                                \
            int _arr = _o >> 8, _row = (_o >> 2) & 63, _seg = _o & 3;               \
            const uint16_t* _src = (_arr ? g_vtl : g_vth)                           \
                + (size_t)(b * HS + _row) * TT + _j0 + _seg * 8;                    \
            cp16(_d + 9216 + _arr * 5120 + _row * 80 + _seg * 16, _src);            \
        }                                                                           \
        CP_COMMIT();                                                                \
    } while (0)

    ISSUE_CHUNK(kb * SPLIT, 0);

    for (int c = 0; c < nch; c++) {
        const int cur = c & 1;
        const int j0  = kb * SPLIT + c * 32;
        CP_WAIT0();
        __syncthreads();
        if (c + 1 < nch) ISSUE_CHUNK(kb * SPLIT + (c + 1) * 32, 1 - cur);

        if (j0 > r0 + 15) continue;        /* warp-uniform skip */
        const uint32_t kB = sb + cur * ABUF;
        const uint32_t vB = kB + 9216;

        float sc[4][4];
        #pragma unroll
        for (int nt = 0; nt < 4; nt++)
            #pragma unroll
            for (int e = 0; e < 4; e++) sc[nt][e] = 0.f;

        #pragma unroll
        for (int nt = 0; nt < 4; nt++) {
            unsigned kh[8], kl[8];
            uint32_t rowoff = kB + (uint32_t)((nt * 8 + l7) * 144 + q4 * 16);
            ldsm_x4(kh,     rowoff);
            ldsm_x4(kh + 4, rowoff + 64);
            ldsm_x4(kl,     rowoff + 4608);
            ldsm_x4(kl + 4, rowoff + 4608 + 64);
            #pragma unroll
            for (int kk = 0; kk < 4; kk++) {
                mma_bf16(sc[nt], qh[kk], kh + kk * 2);
                mma_bf16(sc[nt], qh[kk], kl + kk * 2);
                mma_bf16(sc[nt], ql[kk], kh + kk * 2);
            }
        }

        float mxa = -CUDART_INF_F, mxb = -CUDART_INF_F;
        #pragma unroll
        for (int nt = 0; nt < 4; nt++) {
            int jc = j0 + nt * 8 + 2 * tig;
            if (jc     > ra) sc[nt][0] = -CUDART_INF_F;
            if (jc + 1 > ra) sc[nt][1] = -CUDART_INF_F;
            if (jc     > rb) sc[nt][2] = -CUDART_INF_F;
            if (jc + 1 > rb) sc[nt][3] = -CUDART_INF_F;
            mxa = fmaxf(mxa, fmaxf(sc[nt][0], sc[nt][1]));
            mxb = fmaxf(mxb, fmaxf(sc[nt][2], sc[nt][3]));
        }
        mxa = fmaxf(mxa, __shfl_xor_sync(0xffffffffu, mxa, 1));
        mxa = fmaxf(mxa, __shfl_xor_sync(0xffffffffu, mxa, 2));
        mxb = fmaxf(mxb, __shfl_xor_sync(0xffffffffu, mxb, 1));
        mxb = fmaxf(mxb, __shfl_xor_sync(0xffffffffu, mxb, 2));

        float mna = fmaxf(m_a, mxa), mnb = fmaxf(m_b, mxb);
        float alpha_a = exp2f((m_a - mna) * SCV);
        float alpha_b = exp2f((m_b - mnb) * SCV);
        m_a = mna; m_b = mnb;

        float p[4][4];
        float laa = 0.f, lba = 0.f;
        #pragma unroll
        for (int nt = 0; nt < 4; nt++) {
            p[nt][0] = exp2f((sc[nt][0] - mna) * SCV);
            p[nt][1] = exp2f((sc[nt][1] - mna) * SCV);
            p[nt][2] = exp2f((sc[nt][2] - mnb) * SCV);
            p[nt][3] = exp2f((sc[nt][3] - mnb) * SCV);
            laa += p[nt][0] + p[nt][1];
            lba += p[nt][2] + p[nt][3];
        }
        laa += __shfl_xor_sync(0xffffffffu, laa, 1);
        laa += __shfl_xor_sync(0xffffffffu, laa, 2);
        lba += __shfl_xor_sync(0xffffffffu, lba, 1);
        lba += __shfl_xor_sync(0xffffffffu, lba, 2);
        l_a = l_a * alpha_a + laa;
        l_b = l_b * alpha_b + lba;

        #pragma unroll
        for (int nt = 0; nt < 8; nt++) {
            o[nt][0] *= alpha_a; o[nt][1] *= alpha_a;
            o[nt][2] *= alpha_b; o[nt][3] *= alpha_b;
        }

        unsigned ph[2][4], pl[2][4];
        #pragma unroll
        for (int k2 = 0; k2 < 2; k2++) {
            int n0 = 2 * k2, n1 = 2 * k2 + 1;
            #pragma unroll
            for (int e = 0; e < 4; e++) {
                int nt = (e < 2) ? n0 : n1;
                int e0 = (e & 1) ? 2 : 0;
                float pa = p[nt][e0], pb = p[nt][e0 + 1];
                unsigned hp = pk_bf2(pa, pb);
                float ha = __uint_as_float(hp << 16);
                float hb = __uint_as_float(hp & 0xffff0000u);
                ph[k2][e] = hp;
                pl[k2][e] = pk_bf2(pa - ha, pb - hb);
            }
        }

        #pragma unroll
        for (int nt = 0; nt < 8; nt++) {
            unsigned vh[4], vl[4];
            uint32_t rowoff = vB + (uint32_t)((nt * 8 + l7) * 80 + q4 * 16);
            ldsm_x4(vh, rowoff);
            ldsm_x4(vl, rowoff + 5120);
            #pragma unroll
            for (int k2 = 0; k2 < 2; k2++) {
                mma_bf16(o[nt], ph[k2], vh + k2 * 2);
                mma_bf16(o[nt], ph[k2], vl + k2 * 2);
                mma_bf16(o[nt], pl[k2], vh + k2 * 2);
            }
        }
    }

    size_t pa_off = ((size_t)kb * ROWS + bT + ra) * HS;
    size_t pb_off = ((size_t)kb * ROWS + bT + rb) * HS;
    #pragma unroll
    for (int nt = 0; nt < 8; nt++) {
        *(float2*)&g_po[pa_off + nt * 8 + 2 * tig] = make_float2(o[nt][0], o[nt][1]);
        *(float2*)&g_po[pb_off + nt * 8 + 2 * tig] = make_float2(o[nt][2], o[nt][3]);
    }
    if (tig == 0) {
        g_pm[kb * ROWS + bT + ra] = m_a * 8.0f;
        g_pl[kb * ROWS + bT + ra] = l_a;
        g_pm[kb * ROWS + bT + rb] = m_b * 8.0f;
        g_pl[kb * ROWS + bT + rb] = l_b;
    }
}

/* ---------------- combine split partials (float2/thread) ----------------- */
__global__ __launch_bounds__(256)
void attn_combine_kernel(float* __restrict__ out) {
    int t = blockIdx.x * blockDim.x + threadIdx.x;
    if (t >= ROWS * 32) return;
    int row = t >> 5;
    int d2  = t & 31;
    int smax = (row & (TT - 1)) >> 8;

    float mm[NS], ll[NS];
    #pragma unroll
    for (int s = 0; s < NS; s++) {
        bool a = (s <= smax);
        mm[s] = a ? g_pm[s * ROWS + row] : -CUDART_INF_F;
        ll[s] = a ? g_pl[s * ROWS + row] : 0.f;
    }
    float2 po[NS];
    #pragma unroll
    for (int s = 0; s < NS; s++) {
        po[s] = (s <= smax)
              ? ((const float2*)g_po)[((size_t)s * ROWS + row) * 32 + d2]
              : make_float2(0.f, 0.f);
    }

    float m = -CUDART_INF_F;
    #pragma unroll
    for (int s = 0; s < NS; s++) m = fmaxf(m, mm[s]);

    float l = 0.f;
    float2 acc = make_float2(0.f, 0.f);
    #pragma unroll
    for (int s = 0; s < NS; s++) {
        float wgt = __expf(mm[s] - m);
        l += ll[s] * wgt;
        acc.x = fmaf(wgt, po[s].x, acc.x);
        acc.y = fmaf(wgt, po[s].y, acc.y);
    }
    float inv = 1.f / l;
    ((float2*)out)[(size_t)row * 32 + d2] = make_float2(acc.x * inv, acc.y * inv);
}

/* ---------------- launch ------------------------------------------------ */
extern "C" void kernel_launch(void* const* d_in, const int* in_sizes, int n_in,
                              void* d_out, int out_size) {
    (void)in_sizes; (void)n_in; (void)out_size;
    const float* x  = (const float*)d_in[0];
    const float* Wq = (const float*)d_in[1];
    const float* bq = (const float*)d_in[2];
    const float* Wk = (const float*)d_in[3];
    const float* bk = (const float*)d_in[4];
    const float* Wv = (const float*)d_in[5];

    build_b_kernel<<<NCOL * DM / 256, 256>>>(Wq, Wk, Wv);
    qkv_mma_kernel<<<dim3(ROWS / 128, 3), 256>>>(x, bq, bk);
    attn_mma_kernel<<<dim3(TRI2, BB), 256>>>();
    attn_combine_kernel<<<(ROWS * 32 + 255) / 256, 256>>>((float*)d_out);
}

// round 11
// speedup vs baseline: 1.1296x; 1.1296x over previous
#include <cuda_runtime.h>
#include <cuda_bf16.h>
#include <math_constants.h>
#include <cstdint>

#define DM   1024
#define HS   64
#define BB   4
#define TT   2048
#define ROWS (BB * TT)        /* 8192 */
#define NS   8                /* key splits (SPLIT = 256) */
#define SPLIT 256
#define TRI2 72               /* sum ceil((qt+1)/2), qt=0..15 */
#define NCOL 192
#define SCV  11.541560327111707f   /* 8 * log2(e) */

typedef unsigned long long u64;

/* ---------------- helpers ------------------------------------------------ */
__device__ __forceinline__ unsigned pk_bf2(float a, float b) {
    unsigned r;
    asm("cvt.rn.bf16x2.f32 %0, %1, %2;" : "=r"(r) : "f"(b), "f"(a));
    return r;
}
__device__ __forceinline__ void mma_bf16(float* d, const unsigned* a, const unsigned* b) {
    asm volatile(
        "mma.sync.aligned.m16n8k16.row.col.f32.bf16.bf16.f32 "
        "{%0,%1,%2,%3}, {%4,%5,%6,%7}, {%8,%9}, {%0,%1,%2,%3};"
        : "+f"(d[0]), "+f"(d[1]), "+f"(d[2]), "+f"(d[3])
        : "r"(a[0]), "r"(a[1]), "r"(a[2]), "r"(a[3]), "r"(b[0]), "r"(b[1]));
}
__device__ __forceinline__ void ldsm_x4(unsigned* r, uint32_t addr) {
    asm volatile("ldmatrix.sync.aligned.m8n8.x4.shared.b16 {%0,%1,%2,%3}, [%4];"
        : "=r"(r[0]), "=r"(r[1]), "=r"(r[2]), "=r"(r[3]) : "r"(addr));
}
__device__ __forceinline__ uint32_t smem_u32(const void* p) {
    uint32_t a;
    asm("{ .reg .u64 t; cvta.to.shared.u64 t, %1; cvt.u32.u64 %0, t; }"
        : "=r"(a) : "l"(p));
    return a;
}
__device__ __forceinline__ void split4(float4 v, u64& hi, u64& lo) {
    unsigned h01 = pk_bf2(v.x, v.y), h23 = pk_bf2(v.z, v.w);
    float h0 = __uint_as_float(h01 << 16);
    float h1 = __uint_as_float(h01 & 0xffff0000u);
    float h2 = __uint_as_float(h23 << 16);
    float h3 = __uint_as_float(h23 & 0xffff0000u);
    unsigned l01 = pk_bf2(v.x - h0, v.y - h1), l23 = pk_bf2(v.z - h2, v.w - h3);
    hi = ((u64)h23 << 32) | h01;
    lo = ((u64)l23 << 32) | l01;
}

/* ---------------- device scratch ---------------------------------------- */
__device__ u64 g_Bh[NCOL * DM / 4];
__device__ u64 g_Bl[NCOL * DM / 4];
__device__ uint16_t g_qh[ROWS * HS], g_ql[ROWS * HS];
__device__ uint16_t g_kh[ROWS * HS], g_kl[ROWS * HS];
__device__ uint16_t g_vth[BB * HS * TT], g_vtl[BB * HS * TT];
__device__ float g_po[(size_t)NS * ROWS * HS];
__device__ float g_pm[NS * ROWS];
__device__ float g_pl[NS * ROWS];

/* ---------------- build fused transposed weight B[n][k] ------------------ */
__global__ __launch_bounds__(256)
void build_b_kernel(const float* __restrict__ Wq, const float* __restrict__ Wk,
                    const float* __restrict__ Wv) {
    int i = blockIdx.x * 256 + threadIdx.x;
    int n = i >> 10, k = i & 1023;
    const float* W = (n < 64) ? Wq : ((n < 128) ? Wk : Wv);
    float v = W[(size_t)k * HS + (n & 63)];
    unsigned hp = pk_bf2(v, 0.f);
    float h = __uint_as_float(hp << 16);
    unsigned lp = pk_bf2(v - h, 0.f);
    ((uint16_t*)g_Bh)[i] = (uint16_t)(hp & 0xffffu);
    ((uint16_t*)g_Bl)[i] = (uint16_t)(lp & 0xffffu);
}

/* ---------------- fused QKV GEMM: M=64, N=192 per block (one wave) ------
 * Grid = 128 blocks. 8 warps as 2m x 4n; warp tile 32 x 48 (6 n8-tiles).
 * K chunks of 32, single smem buffer (round-9 pipeline), 16B loaders.
 * smem: Ah[64x80] Al Bh[192x80] Bl = 40960 B; epilogue reuses as sT. */
#define QPITCH 80
#define TPITCH 132
__global__ __launch_bounds__(256)
void qkv_mma_kernel(const float* __restrict__ x,
                    const float* __restrict__ bq, const float* __restrict__ bk) {
    __shared__ __align__(128) uint8_t sbuf[40960];
    uint8_t* sAh = sbuf;
    uint8_t* sAl = sbuf + 5120;
    uint8_t* sBh = sbuf + 10240;
    uint8_t* sBl = sbuf + 25600;
    float*   sT  = (float*)sbuf;     /* 64 x TPITCH fp32 = 33792 B */

    const int tid  = threadIdx.x;
    const int row0 = blockIdx.x * 64;
    const int w    = tid >> 5;
    const int lane = tid & 31;
    const int wm   = w & 1;          /* m group: 32 rows */
    const int wn   = w >> 1;         /* n group: 48 cols */
    const int g    = lane >> 2;
    const int tig  = lane & 3;
    const int l7   = lane & 7;
    const int q01  = (lane >> 3) & 1;
    const int q2   = lane >> 4;
    const uint32_t aBh = smem_u32(sAh), aBl = smem_u32(sAl);
    const uint32_t bBh = smem_u32(sBh), bBl = smem_u32(sBl);

    /* A loader: 1 16B-item/thread: row = tid>>2, seg = tid&3 (16B of bf16 = 8 fp32) */
    const int arow = tid >> 2, aseg = tid & 3;
    /* B loader: 6 16B-items/thread (2 arrays x 3) */
    int brow_[3], bseg_[3];
    #pragma unroll
    for (int t = 0; t < 3; t++) { int i = tid + t * 256; brow_[t] = i >> 2; bseg_[t] = i & 3; }

    float acc[2][6][4];
    #pragma unroll
    for (int mt = 0; mt < 2; mt++)
        #pragma unroll
        for (int nt = 0; nt < 6; nt++)
            #pragma unroll
            for (int e = 0; e < 4; e++) acc[mt][nt][e] = 0.f;

    float4 fa0, fa1;
    ulonglong2 rb[2][3];
    /* prefetch chunk 0 */
    {
        const float* ap = x + (size_t)(row0 + arow) * DM + aseg * 8;
        fa0 = *(const float4*)ap;
        fa1 = *(const float4*)(ap + 4);
        #pragma unroll
        for (int t = 0; t < 3; t++) {
            rb[0][t] = *(const ulonglong2*)(g_Bh + (size_t)brow_[t] * 256 + bseg_[t] * 2);
            rb[1][t] = *(const ulonglong2*)(g_Bl + (size_t)brow_[t] * 256 + bseg_[t] * 2);
        }
    }

    for (int c = 0; c < 32; c++) {
        /* STS chunk c */
        {
            u64 h0, l0, h1, l1;
            split4(fa0, h0, l0);
            split4(fa1, h1, l1);
            ulonglong2 vh; vh.x = h0; vh.y = h1;
            ulonglong2 vl; vl.x = l0; vl.y = l1;
            *(ulonglong2*)(sAh + arow * QPITCH + aseg * 16) = vh;
            *(ulonglong2*)(sAl + arow * QPITCH + aseg * 16) = vl;
            #pragma unroll
            for (int t = 0; t < 3; t++) {
                *(ulonglong2*)(sBh + brow_[t] * QPITCH + bseg_[t] * 16) = rb[0][t];
                *(ulonglong2*)(sBl + brow_[t] * QPITCH + bseg_[t] * 16) = rb[1][t];
            }
        }
        __syncthreads();

        if (c + 1 < 32) {      /* prefetch chunk c+1 (regs only) */
            const float* ap = x + (size_t)(row0 + arow) * DM + (c + 1) * 32 + aseg * 8;
            fa0 = *(const float4*)ap;
            fa1 = *(const float4*)(ap + 4);
            #pragma unroll
            for (int t = 0; t < 3; t++) {
                rb[0][t] = *(const ulonglong2*)(g_Bh + (size_t)brow_[t] * 256
                                                + (c + 1) * 8 + bseg_[t] * 2);
                rb[1][t] = *(const ulonglong2*)(g_Bl + (size_t)brow_[t] * 256
                                                + (c + 1) * 8 + bseg_[t] * 2);
            }
        }

        #pragma unroll
        for (int ks = 0; ks < 2; ks++) {
            unsigned ah[2][4], al[2][4], bh6[3][4], bl6[3][4];
            #pragma unroll
            for (int mt = 0; mt < 2; mt++) {
                uint32_t aoff = (uint32_t)((wm * 32 + mt * 16 + q01 * 8 + l7) * QPITCH
                                           + ks * 32 + q2 * 16);
                ldsm_x4(ah[mt], aBh + aoff);
                ldsm_x4(al[mt], aBl + aoff);
            }
            #pragma unroll
            for (int p = 0; p < 3; p++) {
                uint32_t boff = (uint32_t)((wn * 48 + p * 16 + q2 * 8 + l7) * QPITCH
                                           + ks * 32 + q01 * 16);
                ldsm_x4(bh6[p], bBh + boff);
                ldsm_x4(bl6[p], bBl + boff);
            }
            #pragma unroll
            for (int mt = 0; mt < 2; mt++)
                #pragma unroll
                for (int nt = 0; nt < 6; nt++) {
                    const unsigned* bh = &bh6[nt >> 1][(nt & 1) * 2];
                    const unsigned* bl = &bl6[nt >> 1][(nt & 1) * 2];
                    mma_bf16(acc[mt][nt], ah[mt], bh);
                    mma_bf16(acc[mt][nt], ah[mt], bl);
                    mma_bf16(acc[mt][nt], al[mt], bh);
                }
        }
        __syncthreads();
    }

    /* ---- epilogue: q/k tiles direct, v tiles via smem transpose ---- */
    #pragma unroll
    for (int mt = 0; mt < 2; mt++) {
        #pragma unroll
        for (int nt = 0; nt < 6; nt++) {
            int n_g = wn * 48 + nt * 8;
            int ml  = wm * 32 + mt * 16 + g;
            if (n_g < 128) {
                int which = n_g >> 6;
                int n = (n_g & 63) + tig * 2;
                uint16_t* dh = which ? g_kh : g_qh;
                uint16_t* dl = which ? g_kl : g_ql;
                const float* bias = which ? bk : bq;
                int m = row0 + ml;
                float bx = bias[n], by = bias[n + 1];
                float v0x = acc[mt][nt][0] + bx, v0y = acc[mt][nt][1] + by;
                float v1x = acc[mt][nt][2] + bx, v1y = acc[mt][nt][3] + by;
                unsigned h0 = pk_bf2(v0x, v0y);
                unsigned h1 = pk_bf2(v1x, v1y);
                float h0x = __uint_as_float(h0 << 16);
                float h0y = __uint_as_float(h0 & 0xffff0000u);
                float h1x = __uint_as_float(h1 << 16);
                float h1y = __uint_as_float(h1 & 0xffff0000u);
                *(unsigned*)&dh[(size_t)m * HS + n]       = h0;
                *(unsigned*)&dl[(size_t)m * HS + n]       = pk_bf2(v0x - h0x, v0y - h0y);
                *(unsigned*)&dh[(size_t)(m + 8) * HS + n] = h1;
                *(unsigned*)&dl[(size_t)(m + 8) * HS + n] = pk_bf2(v1x - h1x, v1y - h1y);
            } else {
                int nl = (n_g - 128) + tig * 2;
                sT[nl * TPITCH + ml]           = acc[mt][nt][0];
                sT[(nl + 1) * TPITCH + ml]     = acc[mt][nt][1];
                sT[nl * TPITCH + ml + 8]       = acc[mt][nt][2];
                sT[(nl + 1) * TPITCH + ml + 8] = acc[mt][nt][3];
            }
        }
    }
    __syncthreads();
    {
        const int b  = row0 >> 11;
        const int t0 = row0 & (TT - 1);
        #pragma unroll
        for (int t4 = 0; t4 < 4; t4++) {
            int idx = tid + t4 * 256;          /* 64 d x 16 float4 segs */
            int d = idx >> 4, j = idx & 15;
            float4 v = *(const float4*)&sT[d * TPITCH + 4 * j];
            u64 hi, lo;
            split4(v, hi, lo);
            size_t o = ((size_t)(b * HS + d)) * TT + t0 + 4 * j;
            *(u64*)&g_vth[o] = hi;
            *(u64*)&g_vtl[o] = lo;
        }
    }
}

/* ---------------- causal flash-attention via mma.sync + ldmatrix --------
 * (round-9 structure: single buffer, 64-key chunks, triangle split) */
__global__ __launch_bounds__(256)
void attn_mma_kernel() {
    int t = blockIdx.x;            /* 0..71 */
    int b = blockIdx.y;
    int qt = 0, cum = 0;
    #pragma unroll
    for (int i = 0; i < 16; i++) {
        int cnt = (i + 2) >> 1;
        if (t < cum + cnt) { qt = i; break; }
        cum += cnt;
    }
    const int kb = t - cum;

    const int tid  = threadIdx.x;
    const int w    = tid >> 5;
    const int lane = tid & 31;
    const int g    = lane >> 2;
    const int tig  = lane & 3;
    const int r0   = qt * 128 + w * 16;
    const int bT   = b * TT;
    const int kend = qt * 128 + 128;

    __shared__ __align__(128) uint8_t sKh[64 * 144];
    __shared__ __align__(128) uint8_t sKl[64 * 144];
    __shared__ __align__(128) uint8_t sVh[64 * 144];
    __shared__ __align__(128) uint8_t sVl[64 * 144];

    const uint32_t kBh = smem_u32(sKh), kBl = smem_u32(sKl);
    const uint32_t vBh = smem_u32(sVh), vBl = smem_u32(sVl);
    const int l7 = lane & 7;
    const int q4 = lane >> 3;

    unsigned qh[4][4], ql[4][4];
    {
        const uint16_t* qah = g_qh + (size_t)(bT + r0 + g) * HS;
        const uint16_t* qal = g_ql + (size_t)(bT + r0 + g) * HS;
        #pragma unroll
        for (int kq = 0; kq < 4; kq++) {
            int c = kq * 16 + 2 * tig;
            qh[kq][0] = *(const unsigned*)(qah + c);
            qh[kq][1] = *(const unsigned*)(qah + 8 * HS + c);
            qh[kq][2] = *(const unsigned*)(qah + c + 8);
            qh[kq][3] = *(const unsigned*)(qah + 8 * HS + c + 8);
            ql[kq][0] = *(const unsigned*)(qal + c);
            ql[kq][1] = *(const unsigned*)(qal + 8 * HS + c);
            ql[kq][2] = *(const unsigned*)(qal + c + 8);
            ql[kq][3] = *(const unsigned*)(qal + 8 * HS + c + 8);
        }
    }

    float o[8][4];
    #pragma unroll
    for (int i = 0; i < 8; i++)
        #pragma unroll
        for (int e = 0; e < 4; e++) o[i][e] = 0.f;
    float m_a = -CUDART_INF_F, m_b = -CUDART_INF_F;
    float l_a = 0.f, l_b = 0.f;
    const int ra = r0 + g, rb = r0 + g + 8;

    for (int c2 = 0; c2 < 4; c2++) {
        const int j0 = kb * SPLIT + c2 * 64;
        if (j0 >= kend) break;
        __syncthreads();
        #pragma unroll
        for (int t4 = 0; t4 < 4; t4++) {
            int i = tid + t4 * 256;
            int row = i >> 4, c8 = i & 15;
            *(u64*)(sKh + row * 144 + c8 * 8) =
                *(const u64*)(g_kh + (size_t)(bT + j0 + row) * HS + c8 * 4);
            *(u64*)(sKl + row * 144 + c8 * 8) =
                *(const u64*)(g_kl + (size_t)(bT + j0 + row) * HS + c8 * 4);
            *(u64*)(sVh + row * 144 + c8 * 8) =
                *(const u64*)(g_vth + (size_t)(b * HS + row) * TT + j0 + c8 * 4);
            *(u64*)(sVl + row * 144 + c8 * 8) =
                *(const u64*)(g_vtl + (size_t)(b * HS + row) * TT + j0 + c8 * 4);
        }
        __syncthreads();

        if (j0 > r0 + 15) continue;

        float sc[8][4];
        #pragma unroll
        for (int nt = 0; nt < 8; nt++)
            #pragma unroll
            for (int e = 0; e < 4; e++) sc[nt][e] = 0.f;

        #pragma unroll
        for (int nt = 0; nt < 8; nt++) {
            unsigned kh[8], kl[8];
            uint32_t rowoff = (uint32_t)((nt * 8 + l7) * 144 + q4 * 16);
            ldsm_x4(kh,     kBh + rowoff);
            ldsm_x4(kh + 4, kBh + rowoff + 64);
            ldsm_x4(kl,     kBl + rowoff);
            ldsm_x4(kl + 4, kBl + rowoff + 64);
            #pragma unroll
            for (int kk = 0; kk < 4; kk++) {
                mma_bf16(sc[nt], qh[kk], kh + kk * 2);
                mma_bf16(sc[nt], qh[kk], kl + kk * 2);
                mma_bf16(sc[nt], ql[kk], kh + kk * 2);
            }
        }

        float mxa = -CUDART_INF_F, mxb = -CUDART_INF_F;
        #pragma unroll
        for (int nt = 0; nt < 8; nt++) {
            int jc = j0 + nt * 8 + 2 * tig;
            if (jc     > ra) sc[nt][0] = -CUDART_INF_F;
            if (jc + 1 > ra) sc[nt][1] = -CUDART_INF_F;
            if (jc     > rb) sc[nt][2] = -CUDART_INF_F;
            if (jc + 1 > rb) sc[nt][3] = -CUDART_INF_F;
            mxa = fmaxf(mxa, fmaxf(sc[nt][0], sc[nt][1]));
            mxb = fmaxf(mxb, fmaxf(sc[nt][2], sc[nt][3]));
        }
        mxa = fmaxf(mxa, __shfl_xor_sync(0xffffffffu, mxa, 1));
        mxa = fmaxf(mxa, __shfl_xor_sync(0xffffffffu, mxa, 2));
        mxb = fmaxf(mxb, __shfl_xor_sync(0xffffffffu, mxb, 1));
        mxb = fmaxf(mxb, __shfl_xor_sync(0xffffffffu, mxb, 2));

        float mna = fmaxf(m_a, mxa), mnb = fmaxf(m_b, mxb);
        float alpha_a = exp2f((m_a - mna) * SCV);
        float alpha_b = exp2f((m_b - mnb) * SCV);
        m_a = mna; m_b = mnb;

        float p[8][4];
        float laa = 0.f, lba = 0.f;
        #pragma unroll
        for (int nt = 0; nt < 8; nt++) {
            p[nt][0] = exp2f((sc[nt][0] - mna) * SCV);
            p[nt][1] = exp2f((sc[nt][1] - mna) * SCV);
            p[nt][2] = exp2f((sc[nt][2] - mnb) * SCV);
            p[nt][3] = exp2f((sc[nt][3] - mnb) * SCV);
            laa += p[nt][0] + p[nt][1];
            lba += p[nt][2] + p[nt][3];
        }
        laa += __shfl_xor_sync(0xffffffffu, laa, 1);
        laa += __shfl_xor_sync(0xffffffffu, laa, 2);
        lba += __shfl_xor_sync(0xffffffffu, lba, 1);
        lba += __shfl_xor_sync(0xffffffffu, lba, 2);
        l_a = l_a * alpha_a + laa;
        l_b = l_b * alpha_b + lba;

        #pragma unroll
        for (int nt = 0; nt < 8; nt++) {
            o[nt][0] *= alpha_a; o[nt][1] *= alpha_a;
            o[nt][2] *= alpha_b; o[nt][3] *= alpha_b;
        }

        unsigned ph[4][4], pl[4][4];
        #pragma unroll
        for (int k2 = 0; k2 < 4; k2++) {
            int n0 = 2 * k2, n1 = 2 * k2 + 1;
            #pragma unroll
            for (int e = 0; e < 4; e++) {
                int nt = (e < 2) ? n0 : n1;
                int e0 = (e & 1) ? 2 : 0;
                float pa = p[nt][e0], pb = p[nt][e0 + 1];
                unsigned hp = pk_bf2(pa, pb);
                float ha = __uint_as_float(hp << 16);
                float hb = __uint_as_float(hp & 0xffff0000u);
                ph[k2][e] = hp;
                pl[k2][e] = pk_bf2(pa - ha, pb - hb);
            }
        }

        #pragma unroll
        for (int nt = 0; nt < 8; nt++) {
            unsigned vh[8], vl[8];
            uint32_t rowoff = (uint32_t)((nt * 8 + l7) * 144 + q4 * 16);
            ldsm_x4(vh,     vBh + rowoff);
            ldsm_x4(vh + 4, vBh + rowoff + 64);
            ldsm_x4(vl,     vBl + rowoff);
            ldsm_x4(vl + 4, vBl + rowoff + 64);
            #pragma unroll
            for (int k2 = 0; k2 < 4; k2++) {
                mma_bf16(o[nt], ph[k2], vh + k2 * 2);
                mma_bf16(o[nt], ph[k2], vl + k2 * 2);
                mma_bf16(o[nt], pl[k2], vh + k2 * 2);
            }
        }
    }

    size_t pa_off = ((size_t)kb * ROWS + bT + ra) * HS;
    size_t pb_off = ((size_t)kb * ROWS + bT + rb) * HS;
    #pragma unroll
    for (int nt = 0; nt < 8; nt++) {
        *(float2*)&g_po[pa_off + nt * 8 + 2 * tig] = make_float2(o[nt][0], o[nt][1]);
        *(float2*)&g_po[pb_off + nt * 8 + 2 * tig] = make_float2(o[nt][2], o[nt][3]);
    }
    if (tig == 0) {
        g_pm[kb * ROWS + bT + ra] = m_a * 8.0f;
        g_pl[kb * ROWS + bT + ra] = l_a;
        g_pm[kb * ROWS + bT + rb] = m_b * 8.0f;
        g_pl[kb * ROWS + bT + rb] = l_b;
    }
}

/* ---------------- combine split partials (float2/thread) ----------------- */
__global__ __launch_bounds__(256)
void attn_combine_kernel(float* __restrict__ out) {
    int t = blockIdx.x * blockDim.x + threadIdx.x;
    if (t >= ROWS * 32) return;
    int row = t >> 5;
    int d2  = t & 31;
    int smax = (row & (TT - 1)) >> 8;

    float mm[NS], ll[NS];
    #pragma unroll
    for (int s = 0; s < NS; s++) {
        bool a = (s <= smax);
        mm[s] = a ? g_pm[s * ROWS + row] : -CUDART_INF_F;
        ll[s] = a ? g_pl[s * ROWS + row] : 0.f;
    }
    float2 po[NS];
    #pragma unroll
    for (int s = 0; s < NS; s++) {
        po[s] = (s <= smax)
              ? ((const float2*)g_po)[((size_t)s * ROWS + row) * 32 + d2]
              : make_float2(0.f, 0.f);
    }

    float m = -CUDART_INF_F;
    #pragma unroll
    for (int s = 0; s < NS; s++) m = fmaxf(m, mm[s]);

    float l = 0.f;
    float2 acc = make_float2(0.f, 0.f);
    #pragma unroll
    for (int s = 0; s < NS; s++) {
        float wgt = __expf(mm[s] - m);
        l += ll[s] * wgt;
        acc.x = fmaf(wgt, po[s].x, acc.x);
        acc.y = fmaf(wgt, po[s].y, acc.y);
    }
    float inv = 1.f / l;
    ((float2*)out)[(size_t)row * 32 + d2] = make_float2(acc.x * inv, acc.y * inv);
}

/* ---------------- launch ------------------------------------------------ */
extern "C" void kernel_launch(void* const* d_in, const int* in_sizes, int n_in,
                              void* d_out, int out_size) {
    (void)in_sizes; (void)n_in; (void)out_size;
    const float* x  = (const float*)d_in[0];
    const float* Wq = (const float*)d_in[1];
    const float* bq = (const float*)d_in[2];
    const float* Wk = (const float*)d_in[3];
    const float* bk = (const float*)d_in[4];
    const float* Wv = (const float*)d_in[5];

    build_b_kernel<<<NCOL * DM / 256, 256>>>(Wq, Wk, Wv);
    qkv_mma_kernel<<<ROWS / 64, 256>>>(x, bq, bk);
    attn_mma_kernel<<<dim3(TRI2, BB), 256>>>();
    attn_combine_kernel<<<(ROWS * 32 + 255) / 256, 256>>>((float*)d_out);
}